// round 1
// baseline (speedup 1.0000x reference)
#include <cuda_runtime.h>
#include <math.h>

// Problem dims (fixed by the dataset)
#define Bn   4
#define Cn   256
#define HWn  65536
#define Pn   256
#define THRESH_F 0.8f
#define EPSn 1e-5f

// Scratch (no cudaMalloc allowed)
__device__ int   g_idx[Bn * Pn];
__device__ float g_feat[Bn * Pn * Cn];   // (B, P, C)
__device__ float g_z[Bn * Pn * Cn];      // (B, P, C)

// ---------------------------------------------------------------------------
// Composite sort key: (monotone float key << 32) | (0xFFFFFFFF - index)
// Larger key == larger value; ties -> smaller index wins. Keys are unique.
// ---------------------------------------------------------------------------
__device__ __forceinline__ unsigned long long make_key(float e, int i) {
    float v = (e < THRESH_F) ? 0.0f : e;
    unsigned int ub = __float_as_uint(v);
    ub = (ub & 0x80000000u) ? ~ub : (ub | 0x80000000u);
    return ((unsigned long long)ub << 32) | (unsigned long long)(0xFFFFFFFFu - (unsigned int)i);
}

// ---------------------------------------------------------------------------
// Top-256 per batch via 8-pass byte radix select + compaction + bitonic sort.
// 1 block (1024 threads) per batch.
// ---------------------------------------------------------------------------
__global__ void __launch_bounds__(1024, 1)
topk_kernel(const float* __restrict__ edge, int* __restrict__ out_idx) {
    const int b = blockIdx.x;
    const float* e = edge + (size_t)b * HWn;

    __shared__ unsigned int hist[256];
    __shared__ unsigned long long sh_prefix;
    __shared__ int sh_K;
    __shared__ unsigned long long keys[Pn];
    __shared__ int cnt;

    unsigned long long prefix = 0ull;
    int K = Pn;

    for (int pass = 7; pass >= 0; --pass) {
        const int shift = pass * 8;
        if (threadIdx.x < 256) hist[threadIdx.x] = 0u;
        __syncthreads();

        #pragma unroll 4
        for (int k = 0; k < HWn / 1024; ++k) {
            const int i = threadIdx.x + k * 1024;
            const unsigned long long ck = make_key(e[i], i);
            const bool active = (pass == 7) || ((ck >> (shift + 8)) == prefix);
            const unsigned int bin = (unsigned int)((ck >> shift) & 0xFFull);
            const unsigned int amask = __ballot_sync(0xFFFFFFFFu, active);
            if (active) {
                // warp-aggregated histogram: one atomic per distinct bin per warp
                const unsigned int peers = __match_any_sync(amask, bin);
                const int leader = __ffs(peers) - 1;
                if ((int)(threadIdx.x & 31) == leader)
                    atomicAdd(&hist[bin], (unsigned int)__popc(peers));
            }
        }
        __syncthreads();

        if (threadIdx.x == 0) {
            int k = K;
            int d = 255;
            for (; d >= 0; --d) {
                const int c = (int)hist[d];
                if (k <= c) break;
                k -= c;
            }
            if (d < 0) d = 0;  // safety (invariant guarantees break)
            sh_prefix = (prefix << 8) | (unsigned long long)d;
            sh_K = k;
        }
        __syncthreads();
        prefix = sh_prefix;
        K = sh_K;
        __syncthreads();
    }
    // prefix == exact composite key of the rank-256 element.

    if (threadIdx.x == 0) cnt = 0;
    __syncthreads();

    for (int k = 0; k < HWn / 1024; ++k) {
        const int i = threadIdx.x + k * 1024;
        const unsigned long long ck = make_key(e[i], i);
        if (ck >= prefix) {
            const int p = atomicAdd(&cnt, 1);
            keys[p] = ck;   // exactly 256 (keys unique)
        }
    }
    __syncthreads();

    // Bitonic sort, descending, 256 elements.
    for (int kk = 2; kk <= Pn; kk <<= 1) {
        for (int jj = kk >> 1; jj > 0; jj >>= 1) {
            const int i = threadIdx.x;
            if (i < Pn) {
                const int ixj = i ^ jj;
                if (ixj > i) {
                    const unsigned long long a = keys[i];
                    const unsigned long long c = keys[ixj];
                    const bool up = ((i & kk) == 0);
                    const bool sw = up ? (a < c) : (a > c);
                    if (sw) { keys[i] = c; keys[ixj] = a; }
                }
            }
            __syncthreads();
        }
    }

    if (threadIdx.x < Pn) {
        out_idx[b * Pn + threadIdx.x] =
            (int)(0xFFFFFFFFu - (unsigned int)(keys[threadIdx.x] & 0xFFFFFFFFull));
    }
}

// ---------------------------------------------------------------------------
// Gather: feat[b][n][d] = x[b][d][idx[b][n]]
// grid (Pn, Bn), 256 threads (d)
// ---------------------------------------------------------------------------
__global__ void gather_kernel(const float* __restrict__ x) {
    const int b = blockIdx.y;
    const int n = blockIdx.x;
    const int d = threadIdx.x;
    const int col = g_idx[b * Pn + n];
    g_feat[((b * Pn + n) << 8) + d] =
        x[(size_t)b * Cn * HWn + (size_t)d * HWn + (size_t)col];
}

// ---------------------------------------------------------------------------
// GEMM1 (NN): Z[b,i,d] = relu( BN_adj( sum_j W_adj[i,j]*feat[b,j,d] ) ) + feat[b,i,d]
// 64x64 tiles, 256 threads, 4x4 microtile.
// ---------------------------------------------------------------------------
__global__ void __launch_bounds__(256)
gemm1_kernel(const float* __restrict__ W,
             const float* __restrict__ ga, const float* __restrict__ ba,
             const float* __restrict__ ma, const float* __restrict__ va) {
    __shared__ float sA[16][64 + 4];
    __shared__ float sB[16][64 + 4];

    const int b  = blockIdx.z;
    const float* F = g_feat + b * Pn * Cn;
    float* Z       = g_z    + b * Pn * Cn;
    const int ti = blockIdx.y * 64;
    const int td = blockIdx.x * 64;
    const int tx = threadIdx.x & 15;
    const int ty = threadIdx.x >> 4;

    float acc[4][4] = {};

    for (int k0 = 0; k0 < Pn; k0 += 16) {
        #pragma unroll
        for (int r = 0; r < 4; ++r) {
            const int eI = threadIdx.x + r * 256;
            const int ai = eI >> 4, ak = eI & 15;
            sA[ak][ai] = W[(ti + ai) * Pn + (k0 + ak)];
            const int bk = eI >> 6, bd = eI & 63;
            sB[bk][bd] = F[(k0 + bk) * Cn + (td + bd)];
        }
        __syncthreads();
        #pragma unroll
        for (int k = 0; k < 16; ++k) {
            float a0[4], b0[4];
            #pragma unroll
            for (int u = 0; u < 4; ++u) a0[u] = sA[k][ty * 4 + u];
            #pragma unroll
            for (int u = 0; u < 4; ++u) b0[u] = sB[k][tx * 4 + u];
            #pragma unroll
            for (int i = 0; i < 4; ++i)
                #pragma unroll
                for (int j = 0; j < 4; ++j)
                    acc[i][j] += a0[i] * b0[j];
        }
        __syncthreads();
    }

    #pragma unroll
    for (int ui = 0; ui < 4; ++ui) {
        const int i = ti + ty * 4 + ui;
        const float inv = ga[i] * rsqrtf(va[i] + EPSn);
        const float add = ba[i] - ma[i] * inv;
        #pragma unroll
        for (int ud = 0; ud < 4; ++ud) {
            const int d = td + tx * 4 + ud;
            const float r = fmaxf(acc[ui][ud] * inv + add, 0.0f) + F[i * Cn + d];
            Z[i * Cn + d] = r;
        }
    }
}

// ---------------------------------------------------------------------------
// GEMM2 (NT) + scatter epilogue:
//   z2[b,c,p] = relu( BN_wg( sum_d W_wg[c,d] * Z[b,p,d] ) )
//   out[b, c, idx[b,p]] = z2[b,c,p]
// Computed as C[p,c] = sum_d Z[p,d]*W[c,d]; rows=p, cols=c.
// ---------------------------------------------------------------------------
__global__ void __launch_bounds__(256)
gemm2_kernel(const float* __restrict__ Wg,
             const float* __restrict__ gw, const float* __restrict__ bw,
             const float* __restrict__ mw, const float* __restrict__ vw,
             float* __restrict__ out) {
    __shared__ float sA[16][64 + 4];
    __shared__ float sB[16][64 + 4];

    const int b = blockIdx.z;
    const float* Z = g_z + b * Pn * Cn;
    const int tp = blockIdx.y * 64;
    const int tc = blockIdx.x * 64;
    const int tx = threadIdx.x & 15;
    const int ty = threadIdx.x >> 4;

    float acc[4][4] = {};

    for (int k0 = 0; k0 < Cn; k0 += 16) {
        #pragma unroll
        for (int r = 0; r < 4; ++r) {
            const int eI = threadIdx.x + r * 256;
            const int ar = eI >> 4, ak = eI & 15;
            sA[ak][ar] = Z[(tp + ar) * Cn + (k0 + ak)];
            sB[ak][ar] = Wg[(tc + ar) * Cn + (k0 + ak)];
        }
        __syncthreads();
        #pragma unroll
        for (int k = 0; k < 16; ++k) {
            float a0[4], b0[4];
            #pragma unroll
            for (int u = 0; u < 4; ++u) a0[u] = sA[k][ty * 4 + u];
            #pragma unroll
            for (int u = 0; u < 4; ++u) b0[u] = sB[k][tx * 4 + u];
            #pragma unroll
            for (int i = 0; i < 4; ++i)
                #pragma unroll
                for (int j = 0; j < 4; ++j)
                    acc[i][j] += a0[i] * b0[j];
        }
        __syncthreads();
    }

    // Hoist BN coefficients per column c, then scatter.
    #pragma unroll
    for (int uc = 0; uc < 4; ++uc) {
        const int c = tc + tx * 4 + uc;
        const float inv = gw[c] * rsqrtf(vw[c] + EPSn);
        const float add = bw[c] - mw[c] * inv;
        #pragma unroll
        for (int ui = 0; ui < 4; ++ui) {
            const int p = tp + ty * 4 + ui;
            const int col = g_idx[b * Pn + p];
            const float val = fmaxf(acc[ui][uc] * inv + add, 0.0f);
            out[(size_t)b * Cn * HWn + (size_t)c * HWn + (size_t)col] = val;
        }
    }
}

// ---------------------------------------------------------------------------
extern "C" void kernel_launch(void* const* d_in, const int* in_sizes, int n_in,
                              void* d_out, int out_size) {
    const float* x     = (const float*)d_in[0];
    const float* edge  = (const float*)d_in[1];
    const float* w_adj = (const float*)d_in[2];
    const float* g_adj = (const float*)d_in[3];
    const float* b_adj = (const float*)d_in[4];
    const float* m_adj = (const float*)d_in[5];
    const float* v_adj = (const float*)d_in[6];
    const float* w_wg  = (const float*)d_in[7];
    const float* g_wg  = (const float*)d_in[8];
    const float* b_wg  = (const float*)d_in[9];
    const float* m_wg  = (const float*)d_in[10];
    const float* v_wg  = (const float*)d_in[11];
    float* out = (float*)d_out;

    int* idx_ptr = nullptr;
    cudaGetSymbolAddress((void**)&idx_ptr, g_idx);

    // 1) Bulk copy x -> out (dominant cost; issue first).
    cudaMemcpyAsync(out, x, (size_t)Bn * Cn * HWn * sizeof(float),
                    cudaMemcpyDeviceToDevice, 0);

    // 2) Exact top-256 indices per batch.
    topk_kernel<<<Bn, 1024>>>(edge, idx_ptr);

    // 3) Gather point features.
    gather_kernel<<<dim3(Pn, Bn), Cn>>>(x);

    // 4) GCN stage 1 (adjacency mix + BN + ReLU + residual).
    gemm1_kernel<<<dim3(4, 4, Bn), 256>>>(w_adj, g_adj, b_adj, m_adj, v_adj);

    // 5) GCN stage 2 (feature transform + BN + ReLU) fused with scatter into out.
    gemm2_kernel<<<dim3(4, 4, Bn), 256>>>(w_wg, g_wg, b_wg, m_wg, v_wg, out);
}